// round 14
// baseline (speedup 1.0000x reference)
#include <cuda_runtime.h>

#define DIM 4096
#define NTHREADS 256

// FWHT-4096, one CTA per row, zero shuffles, <=32 regs (8 CTAs/SM = 64 warps).
// Champion structure (R4): 2 barriers, 16KB smem, all accesses conflict-free.
// Loads use the default (allocating) policy — evict-first loads measured
// slightly worse; stores keep .cs (output is write-once, never re-read).
//   pass1: local FWHT16 over {e0,e1,e10,e11}  (float4 loads at i=4t+1024c)
//   ex1:   smem gather of {e2..e5} (stride-4), local FWHT16, in-place writeback
//          addresses: P ^ 4n with P = base1 ^ X  (base1 bits2-5 == 0)
//   ex2:   smem gather of {e6..e9} (stride-64), local FWHT16, scale, store
// Global swizzle phys = L ^ (((L>>6)&7)<<2): conflict-free everywhere.
__global__ void __launch_bounds__(NTHREADS, 8)
fwht4096_kernel(const float* __restrict__ x, float* __restrict__ out)
{
    __shared__ float sm[DIM];

    const int t = threadIdx.x;
    const long long row = blockIdx.x;
    const float* __restrict__ px = x + row * (long long)DIM + 4 * t;

    float v[16];
    #pragma unroll
    for (int c = 0; c < 4; ++c) {
        float4 a = *reinterpret_cast<const float4*>(px + 1024 * c);
        v[4*c+0] = a.x; v[4*c+1] = a.y; v[4*c+2] = a.z; v[4*c+3] = a.w;
    }

    // ---- pass1: FWHT16 over v-index bits (dims e0,e1,e10,e11) ----
    #pragma unroll
    for (int s = 0; s < 4; ++s) {
        const int h = 1 << s;
        #pragma unroll
        for (int j = 0; j < 16; ++j) {
            if ((j & h) == 0) {
                float a = v[j], b = v[j + h];
                v[j]     = a + b;
                v[j + h] = a - b;
            }
        }
    }

    // ---- exchange 1 write: float4 at logical 4t+1024c, swizzled ----
    {
        const int wb = (4 * t) ^ (((t >> 4) & 7) << 2);
        #pragma unroll
        for (int c = 0; c < 4; ++c) {
            *reinterpret_cast<float4*>(&sm[wb + 1024 * c]) =
                make_float4(v[4*c+0], v[4*c+1], v[4*c+2], v[4*c+3]);
        }
    }
    __syncthreads();

    // ---- exchange 1: gather dims e2..e5 (stride-4 words), swizzled ----
    // logical L = (t&3) + 4n + 64*((t>>2)&15) + 1024*(t>>6)
    // phys     = P ^ 4n,  P = base1 ^ X  (base1 bits 2-5 are zero)
    const int base1 = (t & 3) + 64 * ((t >> 2) & 15) + 1024 * (t >> 6);
    const int P = base1 ^ (((t >> 2) & 7) << 2);
    #pragma unroll
    for (int n = 0; n < 16; ++n) v[n] = sm[P ^ (4 * n)];

    // FWHT16 over n (dims e2..e5)
    #pragma unroll
    for (int s = 0; s < 4; ++s) {
        const int h = 1 << s;
        #pragma unroll
        for (int j = 0; j < 16; ++j) {
            if ((j & h) == 0) {
                float a = v[j], b = v[j + h];
                v[j]     = a + b;
                v[j + h] = a - b;
            }
        }
    }

    // in-place writeback (per-thread-disjoint slots)
    #pragma unroll
    for (int n = 0; n < 16; ++n) sm[P ^ (4 * n)] = v[n];
    __syncthreads();

    // ---- exchange 2: gather dims e6..e9 (stride-64 words), swizzled ----
    // logical L = (t&63) + 64m + 1024*(t>>6); phys = (base2 ^ 4*(m&7)) + 64m
    const int base2 = (t & 63) + 1024 * (t >> 6);
    #pragma unroll
    for (int m = 0; m < 16; ++m) {
        v[m] = sm[(base2 ^ (4 * (m & 7))) + 64 * m];
    }

    // FWHT16 over m (dims e6..e9)
    #pragma unroll
    for (int s = 0; s < 4; ++s) {
        const int h = 1 << s;
        #pragma unroll
        for (int j = 0; j < 16; ++j) {
            if ((j & h) == 0) {
                float a = v[j], b = v[j + h];
                v[j]     = a + b;
                v[j + h] = a - b;
            }
        }
    }

    // ---- scale (exact 1/64) + coalesced streaming stores ----
    const float SCALE = 0.015625f;
    float* __restrict__ po = out + row * (long long)DIM + base2;
    #pragma unroll
    for (int m = 0; m < 16; ++m) {
        __stcs(&po[64 * m], v[m] * SCALE);
    }
}

extern "C" void kernel_launch(void* const* d_in, const int* in_sizes, int n_in,
                              void* d_out, int out_size)
{
    const float* x = (const float*)d_in[0];
    float* out = (float*)d_out;
    const int rows = in_sizes[0] / DIM;   // 8192
    fwht4096_kernel<<<rows, NTHREADS>>>(x, out);
}